// round 4
// baseline (speedup 1.0000x reference)
#include <cuda_runtime.h>
#include <cstdint>

#define H 8
#define D 32
#define HD 256
#define NC 10000
#define NS 1024
#define ECC 120000
#define ECS 10000
#define ALPHA 0.2f

#define OUT_C_N   (NC * HD)           // 2,560,000 per C type
#define OUT_S_OFF (3 * OUT_C_N)       // 7,680,000
#define OUT_TOTAL (OUT_S_OFF + NS * HD)

// ---------------- device scratch (static, allocation-free) ----------------
__device__ float g_Wh_cc[9 * NC * HD];     // projected src feats per cc relation
__device__ float g_Wh_cs[3 * NC * HD];     // projected src feats per cs relation
__device__ float g_Wh_node[3 * NC * HD];   // self projections (dst attention feats)
__device__ float g_as_cc[9 * NC * H];
__device__ float g_ad_cc[9 * NC * H];
__device__ float g_as_cs[3 * NC * H];
__device__ float g_ad_cs[3 * NS * H];
__device__ float g_ss_cc[9 * NC * H];      // softmax denominators
__device__ float g_ss_cs[3 * NS * H];

// vectorized fp32 reduction (PTX >= 8.1, sm_90+)
__device__ __forceinline__ void red_add_v4(float* addr, float a, float b, float c, float d) {
    asm volatile("red.global.add.v4.f32 [%0], {%1,%2,%3,%4};"
                 :: "l"(addr), "f"(a), "f"(b), "f"(c), "f"(d) : "memory");
}

// ---------------- zero init ----------------
__global__ void zero_kernel(float* __restrict__ out) {
    int stride = gridDim.x * blockDim.x;
    int i0 = blockIdx.x * blockDim.x + threadIdx.x;
    for (int i = i0; i < OUT_S_OFF; i += stride) out[i] = 0.f;        // out_C accumulators
    for (int i = i0; i < 9 * NC * H; i += stride) g_ss_cc[i] = 0.f;
    for (int i = i0; i < 3 * NS * H; i += stride) g_ss_cs[i] = 0.f;
}

// ---------------- fp32 projection GEMM: C[M,256] = A[M,K] @ W[r][K,256] + b[r] ----------------
// block: 256 threads, tile = 32 rows x 256 cols. thread = 8 rows x 4 cols.
// mode 0: cc  -> writes g_Wh_cc[r]   (src type = r/3)
// mode 1: node-> writes g_Wh_node[r] (src type = r)
// mode 2: cs  -> writes g_Wh_cs[r]   (src type = r)
// mode 3: in  -> writes Cout (d_out state region), A = feat_state
// NOTE: scratch outputs are selected via __device__ symbols *inside device code*;
// passing a __device__ symbol as a host-side kernel arg yields the host shadow
// address (and on GB300/ATS silently writes host memory). That was the R3 bug.
__global__ void gemm_proj(const float* __restrict__ f0, const float* __restrict__ f1,
                          const float* __restrict__ f2, const float* __restrict__ fs,
                          const float* __restrict__ W, const float* __restrict__ Bb,
                          float* __restrict__ Cout, int M, int K, int mode) {
    int r = blockIdx.y;
    const float* A;
    float* Cr;
    if (mode == 3) {
        A = fs;
        Cr = Cout;
    } else {
        int s = (mode == 0) ? (r / 3) : r;
        A = (s == 0) ? f0 : (s == 1) ? f1 : f2;
        float* base = (mode == 0) ? g_Wh_cc : (mode == 1) ? g_Wh_node : g_Wh_cs;
        Cr = base + (size_t)r * NC * HD;
    }
    const float* Wr = W + (size_t)r * K * HD;
    const float* Br = Bb + (size_t)r * HD;

    __shared__ float xs[32 * 128];
    int row0 = blockIdx.x * 32;
    int tid = threadIdx.x;

    for (int i = tid; i < 32 * K; i += 256) {
        int rr = i / K, kk = i - rr * K;
        int grow = row0 + rr;
        xs[rr * K + kk] = (grow < M) ? A[(size_t)grow * K + kk] : 0.f;
    }
    __syncthreads();

    int tx = tid & 63;        // 64 column groups * 4 cols
    int ty = tid >> 6;        // 4 row groups * 8 rows
    int c = tx * 4;
    const float* xsp = xs + (ty * 8) * K;

    float acc[8][4];
#pragma unroll
    for (int i = 0; i < 8; i++)
#pragma unroll
        for (int j = 0; j < 4; j++) acc[i][j] = 0.f;

#pragma unroll 4
    for (int k = 0; k < K; k++) {
        float4 w = *(const float4*)(Wr + (size_t)k * HD + c);
#pragma unroll
        for (int i = 0; i < 8; i++) {
            float x = xsp[i * K + k];
            acc[i][0] += x * w.x; acc[i][1] += x * w.y;
            acc[i][2] += x * w.z; acc[i][3] += x * w.w;
        }
    }
    float4 bb = *(const float4*)(Br + c);
#pragma unroll
    for (int i = 0; i < 8; i++) {
        int grow = row0 + ty * 8 + i;
        if (grow < M) {
            float4 o;
            o.x = acc[i][0] + bb.x; o.y = acc[i][1] + bb.y;
            o.z = acc[i][2] + bb.z; o.w = acc[i][3] + bb.w;
            *(float4*)(Cr + (size_t)grow * HD + c) = o;
        }
    }
}

// ---------------- attention dot products ----------------
// a_s_cc[r][i][h] = Wh_cc[r][i][h]·attn_cc[r,0,h], a_d_cc[r][i][h] = Wh_node[r%3][i][h]·attn_cc[r,1,h]
__global__ void adot_cc_kernel(const float* __restrict__ attn) {
    int r = blockIdx.y;
    int idx = blockIdx.x * blockDim.x + threadIdx.x;
    if (idx >= NC * H) return;
    int i = idx >> 3, h = idx & 7;
    const float4* wsp = (const float4*)(g_Wh_cc + ((size_t)(r * NC + i)) * HD + h * D);
    const float4* avs = (const float4*)(attn + ((size_t)(r * 2 + 0) * H + h) * D);
    const float4* wdp = (const float4*)(g_Wh_node + ((size_t)((r % 3) * NC + i)) * HD + h * D);
    const float4* avd = (const float4*)(attn + ((size_t)(r * 2 + 1) * H + h) * D);
    float ss = 0.f, sd = 0.f;
#pragma unroll
    for (int j = 0; j < 8; j++) {
        float4 a = wsp[j], b = avs[j];
        ss += a.x * b.x + a.y * b.y + a.z * b.z + a.w * b.w;
        float4 cdat = wdp[j], dvec = avd[j];
        sd += cdat.x * dvec.x + cdat.y * dvec.y + cdat.z * dvec.z + cdat.w * dvec.w;
    }
    g_as_cc[(size_t)r * NC * H + idx] = ss;
    g_ad_cc[(size_t)r * NC * H + idx] = sd;
}

__global__ void adot_cs_src_kernel(const float* __restrict__ attn) {
    int r = blockIdx.y;
    int idx = blockIdx.x * blockDim.x + threadIdx.x;
    if (idx >= NC * H) return;
    int i = idx >> 3, h = idx & 7;
    const float4* wsp = (const float4*)(g_Wh_cs + ((size_t)(r * NC + i)) * HD + h * D);
    const float4* avs = (const float4*)(attn + ((size_t)(r * 2 + 0) * H + h) * D);
    float ss = 0.f;
#pragma unroll
    for (int j = 0; j < 8; j++) {
        float4 a = wsp[j], b = avs[j];
        ss += a.x * b.x + a.y * b.y + a.z * b.z + a.w * b.w;
    }
    g_as_cs[(size_t)r * NC * H + idx] = ss;
}

// dst attention feats for state = Wh_in (already written to d_out's out_S region)
__global__ void adot_cs_dst_kernel(const float* __restrict__ attn, const float* __restrict__ wh_in) {
    int r = blockIdx.y;
    int idx = blockIdx.x * blockDim.x + threadIdx.x;
    if (idx >= NS * H) return;
    int i = idx >> 3, h = idx & 7;
    const float4* wdp = (const float4*)(wh_in + (size_t)i * HD + h * D);
    const float4* avd = (const float4*)(attn + ((size_t)(r * 2 + 1) * H + h) * D);
    float sd = 0.f;
#pragma unroll
    for (int j = 0; j < 8; j++) {
        float4 a = wdp[j], b = avd[j];
        sd += a.x * b.x + a.y * b.y + a.z * b.z + a.w * b.w;
    }
    g_ad_cs[(size_t)r * NS * H + idx] = sd;
}

// ---------------- pass 1: softmax denominators (no max shift needed; |e| <= ~12) ----------------
__global__ void edge_soft_cc(const int* __restrict__ esrc, const int* __restrict__ edst) {
    int r = blockIdx.y;
    int e = blockIdx.x * blockDim.x + threadIdx.x;
    if (e >= ECC) return;
    int src = esrc[(size_t)r * ECC + e];
    int dst = edst[(size_t)r * ECC + e];
    const float* as = g_as_cc + ((size_t)r * NC + src) * H;
    const float* ad = g_ad_cc + ((size_t)r * NC + dst) * H;
    float4 s0 = *(const float4*)as, s1 = *(const float4*)(as + 4);
    float4 d0 = *(const float4*)ad, d1 = *(const float4*)(ad + 4);
    float ex[8];
    float v[8] = {s0.x + d0.x, s0.y + d0.y, s0.z + d0.z, s0.w + d0.w,
                  s1.x + d1.x, s1.y + d1.y, s1.z + d1.z, s1.w + d1.w};
#pragma unroll
    for (int h = 0; h < 8; h++) {
        float t = v[h] > 0.f ? v[h] : ALPHA * v[h];
        ex[h] = __expf(t);
    }
    float* sp = g_ss_cc + ((size_t)r * NC + dst) * H;
    red_add_v4(sp, ex[0], ex[1], ex[2], ex[3]);
    red_add_v4(sp + 4, ex[4], ex[5], ex[6], ex[7]);
}

__global__ void edge_soft_cs(const int* __restrict__ esrc, const int* __restrict__ edst) {
    int r = blockIdx.y;
    int e = blockIdx.x * blockDim.x + threadIdx.x;
    if (e >= ECS) return;
    int src = esrc[(size_t)r * ECS + e];
    int dst = edst[(size_t)r * ECS + e];
    const float* as = g_as_cs + ((size_t)r * NC + src) * H;
    const float* ad = g_ad_cs + ((size_t)r * NS + dst) * H;
    float4 s0 = *(const float4*)as, s1 = *(const float4*)(as + 4);
    float4 d0 = *(const float4*)ad, d1 = *(const float4*)(ad + 4);
    float ex[8];
    float v[8] = {s0.x + d0.x, s0.y + d0.y, s0.z + d0.z, s0.w + d0.w,
                  s1.x + d1.x, s1.y + d1.y, s1.z + d1.z, s1.w + d1.w};
#pragma unroll
    for (int h = 0; h < 8; h++) {
        float t = v[h] > 0.f ? v[h] : ALPHA * v[h];
        ex[h] = __expf(t);
    }
    float* sp = g_ss_cs + ((size_t)r * NS + dst) * H;
    red_add_v4(sp, ex[0], ex[1], ex[2], ex[3]);
    red_add_v4(sp + 4, ex[4], ex[5], ex[6], ex[7]);
}

// ---------------- pass 2: weighted message aggregation (warp per edge) ----------------
__global__ void edge_msg_cc(const int* __restrict__ esrc, const int* __restrict__ edst,
                            float* __restrict__ out) {
    int r = blockIdx.y;
    int e = blockIdx.x * (blockDim.x >> 5) + (threadIdx.x >> 5);
    if (e >= ECC) return;
    int lane = threadIdx.x & 31;
    int src = esrc[(size_t)r * ECC + e];
    int dst = edst[(size_t)r * ECC + e];
    int h = lane >> 2;
    size_t bs = ((size_t)r * NC + src) * H;
    size_t bd = ((size_t)r * NC + dst) * H;
    float a = g_as_cc[bs + h] + g_ad_cc[bd + h];
    a = a > 0.f ? a : ALPHA * a;
    float w = __expf(a) / g_ss_cc[bd + h];
    const float4* wh = (const float4*)(g_Wh_cc + ((size_t)r * NC + src) * HD);
    float4 v0 = wh[lane * 2], v1 = wh[lane * 2 + 1];
    float* ob = out + (size_t)(r % 3) * OUT_C_N + (size_t)dst * HD + lane * 8;
    red_add_v4(ob, v0.x * w, v0.y * w, v0.z * w, v0.w * w);
    red_add_v4(ob + 4, v1.x * w, v1.y * w, v1.z * w, v1.w * w);
}

__global__ void edge_msg_cs(const int* __restrict__ esrc, const int* __restrict__ edst,
                            float* __restrict__ out) {
    int r = blockIdx.y;
    int e = blockIdx.x * (blockDim.x >> 5) + (threadIdx.x >> 5);
    if (e >= ECS) return;
    int lane = threadIdx.x & 31;
    int src = esrc[(size_t)r * ECS + e];
    int dst = edst[(size_t)r * ECS + e];
    int h = lane >> 2;
    float a = g_as_cs[((size_t)r * NC + src) * H + h] + g_ad_cs[((size_t)r * NS + dst) * H + h];
    a = a > 0.f ? a : ALPHA * a;
    float w = __expf(a) / g_ss_cs[((size_t)r * NS + dst) * H + h];
    const float4* wh = (const float4*)(g_Wh_cs + ((size_t)r * NC + src) * HD);
    float4 v0 = wh[lane * 2], v1 = wh[lane * 2 + 1];
    float* ob = out + (size_t)OUT_S_OFF + (size_t)dst * HD + lane * 8;
    red_add_v4(ob, v0.x * w, v0.y * w, v0.z * w, v0.w * w);
    red_add_v4(ob + 4, v1.x * w, v1.y * w, v1.z * w, v1.w * w);
}

// ---------------- final relu in place ----------------
__global__ void relu_kernel(float* __restrict__ out) {
    int stride = gridDim.x * blockDim.x;
    for (int i = blockIdx.x * blockDim.x + threadIdx.x; i < OUT_TOTAL; i += stride) {
        float v = out[i];
        out[i] = v > 0.f ? v : 0.f;
    }
}

// ---------------- launch ----------------
extern "C" void kernel_launch(void* const* d_in, const int* in_sizes, int n_in,
                              void* d_out, int out_size) {
    const float* feat_C1 = (const float*)d_in[0];
    const float* feat_C2 = (const float*)d_in[1];
    const float* feat_C3 = (const float*)d_in[2];
    const float* feat_state = (const float*)d_in[3];
    const float* W_node = (const float*)d_in[4];
    const float* b_node = (const float*)d_in[5];
    const float* W_cc = (const float*)d_in[6];
    const float* b_cc = (const float*)d_in[7];
    const float* W_cs = (const float*)d_in[8];
    const float* b_cs = (const float*)d_in[9];
    const float* W_in = (const float*)d_in[10];
    const float* b_in = (const float*)d_in[11];
    const float* attn_cc = (const float*)d_in[12];
    const float* attn_cs = (const float*)d_in[13];
    const int* e_cc_src = (const int*)d_in[14];
    const int* e_cc_dst = (const int*)d_in[15];
    const int* e_cs_src = (const int*)d_in[16];
    const int* e_cs_dst = (const int*)d_in[17];
    float* out = (float*)d_out;
    (void)in_sizes; (void)n_in; (void)out_size;

    zero_kernel<<<2048, 256>>>(out);

    dim3 gcc((NC + 31) / 32, 9);
    gemm_proj<<<gcc, 256>>>(feat_C1, feat_C2, feat_C3, feat_state, W_cc, b_cc,
                            nullptr, NC, 128, 0);
    dim3 gn((NC + 31) / 32, 3);
    gemm_proj<<<gn, 256>>>(feat_C1, feat_C2, feat_C3, feat_state, W_node, b_node,
                           nullptr, NC, 128, 1);
    gemm_proj<<<gn, 256>>>(feat_C1, feat_C2, feat_C3, feat_state, W_cs, b_cs,
                           nullptr, NC, 128, 2);
    dim3 gin((NS + 31) / 32, 1);
    gemm_proj<<<gin, 256>>>(feat_C1, feat_C2, feat_C3, feat_state, W_in, b_in,
                            out + OUT_S_OFF, NS, 64, 3);

    dim3 gadc((NC * H + 255) / 256, 9);
    adot_cc_kernel<<<gadc, 256>>>(attn_cc);
    dim3 gads((NC * H + 255) / 256, 3);
    adot_cs_src_kernel<<<gads, 256>>>(attn_cs);
    dim3 gadd((NS * H + 255) / 256, 3);
    adot_cs_dst_kernel<<<gadd, 256>>>(attn_cs, out + OUT_S_OFF);

    dim3 gs1((ECC + 255) / 256, 9);
    edge_soft_cc<<<gs1, 256>>>(e_cc_src, e_cc_dst);
    dim3 gs2((ECS + 255) / 256, 3);
    edge_soft_cs<<<gs2, 256>>>(e_cs_src, e_cs_dst);

    dim3 gm1((ECC + 7) / 8, 9);   // 8 warps/block, warp per edge
    edge_msg_cc<<<gm1, 256>>>(e_cc_src, e_cc_dst, out);
    dim3 gm2((ECS + 7) / 8, 3);
    edge_msg_cs<<<gm2, 256>>>(e_cs_src, e_cs_dst, out);

    relu_kernel<<<4096, 256>>>(out);
}

// round 5
// speedup vs baseline: 1.5121x; 1.5121x over previous
#include <cuda_runtime.h>
#include <cstdint>

#define H 8
#define D 32
#define HD 256
#define NC 10000
#define NS 1024
#define ECC 120000
#define ECS 10000
#define ALPHA 0.2f

#define OUT_C_N   (NC * HD)
#define OUT_S_OFF (3 * OUT_C_N)

// ---------------- device scratch (static, allocation-free) ----------------
__device__ float g_Wh_cc[9 * NC * HD];
__device__ float g_Wh_cs[3 * NC * HD];
__device__ float g_Wh_node[3 * NC * HD];
__device__ float g_Wh_in[NS * HD];
__device__ float g_as_cc[9 * NC * H];
__device__ float g_ad_cc[9 * NC * H];
__device__ float g_as_cs[3 * NC * H];
__device__ float g_ad_cs[3 * NS * H];
// CSR scratch
__device__ int g_cur_cc[9 * NC];
__device__ int g_off_cc[9 * (NC + 1)];
__device__ int g_csr_cc[9 * ECC];
__device__ int g_cur_cs[3 * NS];
__device__ int g_off_cs[3 * (NS + 1)];
__device__ int g_csr_cs[3 * ECS];

// ---------------- zero degree counters ----------------
__global__ void zero_deg_kernel() {
    int i = blockIdx.x * blockDim.x + threadIdx.x;
    int stride = gridDim.x * blockDim.x;
    for (int j = i; j < 9 * NC; j += stride) g_cur_cc[j] = 0;
    for (int j = i; j < 3 * NS; j += stride) g_cur_cs[j] = 0;
}

// ---------------- 128x128 double-buffered fp32 GEMM ----------------
// C[M,256 cols, this block: col0..col0+128] = A[M,K] @ W[r][K,256] + b[r]
// 256 threads, thread computes 8x8 = rows {ty*4+i, 64+ty*4+i} x cols {tx*4+j, 64+tx*4+j}
// mode 0: cc  -> g_Wh_cc[r],  src type r/3
// mode 1: node-> g_Wh_node[r], src type r
// mode 2: cs  -> g_Wh_cs[r],  src type r
// mode 3: in  -> g_Wh_in,     A = feat_state
// (outputs selected via __device__ symbols in device code — never pass symbols from host)
__global__ __launch_bounds__(256, 2)
void gemm128(const float* __restrict__ f0, const float* __restrict__ f1,
             const float* __restrict__ f2, const float* __restrict__ fs,
             const float* __restrict__ W, const float* __restrict__ Bb,
             int M, int K, int mode) {
    int r = blockIdx.z;
    const float* A;
    float* Cbase;
    if (mode == 3) { A = fs; Cbase = g_Wh_in; }
    else {
        int s = (mode == 0) ? (r / 3) : r;
        A = (s == 0) ? f0 : (s == 1) ? f1 : f2;
        float* base = (mode == 0) ? g_Wh_cc : (mode == 1) ? g_Wh_node : g_Wh_cs;
        Cbase = base + (size_t)r * NC * HD;
    }
    const float* Wr = W + (size_t)r * K * HD;
    const float* Br = Bb + (size_t)r * HD;

    __shared__ float As[2][8][128];
    __shared__ float Bs[2][8][128];

    int row0 = blockIdx.x * 128;
    int col0 = blockIdx.y * 128;
    int t = threadIdx.x;
    int arow = t >> 1, ak = (t & 1) * 4;      // A tile load: 128 rows x 8 k
    int bk = t >> 5, bcol = (t & 31) * 4;     // B tile load: 8 k x 128 cols
    int tx = t & 15, ty = t >> 4;

    int nk = K >> 3;

    // stage 0 load
    float4 av, bv;
    {
        int gr = row0 + arow;
        av = (gr < M) ? *(const float4*)(A + (size_t)gr * K + ak)
                      : make_float4(0.f, 0.f, 0.f, 0.f);
        bv = *(const float4*)(Wr + (size_t)bk * HD + col0 + bcol);
        As[0][ak + 0][arow] = av.x; As[0][ak + 1][arow] = av.y;
        As[0][ak + 2][arow] = av.z; As[0][ak + 3][arow] = av.w;
        *(float4*)&Bs[0][bk][bcol] = bv;
    }
    __syncthreads();

    float acc[8][8];
#pragma unroll
    for (int i = 0; i < 8; i++)
#pragma unroll
        for (int j = 0; j < 8; j++) acc[i][j] = 0.f;

    for (int kt = 0; kt < nk; kt++) {
        int cur = kt & 1;
        float4 an, bn;
        if (kt + 1 < nk) {
            int gr = row0 + arow;
            an = (gr < M) ? *(const float4*)(A + (size_t)gr * K + (kt + 1) * 8 + ak)
                          : make_float4(0.f, 0.f, 0.f, 0.f);
            bn = *(const float4*)(Wr + (size_t)((kt + 1) * 8 + bk) * HD + col0 + bcol);
        }
#pragma unroll
        for (int k = 0; k < 8; k++) {
            float a0[8], b0[8];
            *(float4*)(a0)     = *(const float4*)&As[cur][k][ty * 4];
            *(float4*)(a0 + 4) = *(const float4*)&As[cur][k][64 + ty * 4];
            *(float4*)(b0)     = *(const float4*)&Bs[cur][k][tx * 4];
            *(float4*)(b0 + 4) = *(const float4*)&Bs[cur][k][64 + tx * 4];
#pragma unroll
            for (int i = 0; i < 8; i++)
#pragma unroll
                for (int j = 0; j < 8; j++) acc[i][j] += a0[i] * b0[j];
        }
        if (kt + 1 < nk) {
            int nxt = cur ^ 1;
            As[nxt][ak + 0][arow] = an.x; As[nxt][ak + 1][arow] = an.y;
            As[nxt][ak + 2][arow] = an.z; As[nxt][ak + 3][arow] = an.w;
            *(float4*)&Bs[nxt][bk][bcol] = bn;
            __syncthreads();
        }
    }

    float4 bb0 = *(const float4*)(Br + col0 + tx * 4);
    float4 bb1 = *(const float4*)(Br + col0 + 64 + tx * 4);
#pragma unroll
    for (int half = 0; half < 2; half++) {
#pragma unroll
        for (int ii = 0; ii < 4; ii++) {
            int gr = row0 + half * 64 + ty * 4 + ii;
            if (gr < M) {
                int ai = half * 4 + ii;
                float4 o0, o1;
                o0.x = acc[ai][0] + bb0.x; o0.y = acc[ai][1] + bb0.y;
                o0.z = acc[ai][2] + bb0.z; o0.w = acc[ai][3] + bb0.w;
                o1.x = acc[ai][4] + bb1.x; o1.y = acc[ai][5] + bb1.y;
                o1.z = acc[ai][6] + bb1.z; o1.w = acc[ai][7] + bb1.w;
                *(float4*)(Cbase + (size_t)gr * HD + col0 + tx * 4) = o0;
                *(float4*)(Cbase + (size_t)gr * HD + col0 + 64 + tx * 4) = o1;
            }
        }
    }
}

// ---------------- attention dot products ----------------
__global__ void adot_cc_kernel(const float* __restrict__ attn) {
    int r = blockIdx.y;
    int idx = blockIdx.x * blockDim.x + threadIdx.x;
    if (idx >= NC * H) return;
    int i = idx >> 3, h = idx & 7;
    const float4* wsp = (const float4*)(g_Wh_cc + ((size_t)(r * NC + i)) * HD + h * D);
    const float4* avs = (const float4*)(attn + ((size_t)(r * 2 + 0) * H + h) * D);
    const float4* wdp = (const float4*)(g_Wh_node + ((size_t)((r % 3) * NC + i)) * HD + h * D);
    const float4* avd = (const float4*)(attn + ((size_t)(r * 2 + 1) * H + h) * D);
    float ss = 0.f, sd = 0.f;
#pragma unroll
    for (int j = 0; j < 8; j++) {
        float4 a = wsp[j], b = avs[j];
        ss += a.x * b.x + a.y * b.y + a.z * b.z + a.w * b.w;
        float4 c = wdp[j], dv = avd[j];
        sd += c.x * dv.x + c.y * dv.y + c.z * dv.z + c.w * dv.w;
    }
    g_as_cc[(size_t)r * NC * H + idx] = ss;
    g_ad_cc[(size_t)r * NC * H + idx] = sd;
}

__global__ void adot_cs_src_kernel(const float* __restrict__ attn) {
    int r = blockIdx.y;
    int idx = blockIdx.x * blockDim.x + threadIdx.x;
    if (idx >= NC * H) return;
    int i = idx >> 3, h = idx & 7;
    const float4* wsp = (const float4*)(g_Wh_cs + ((size_t)(r * NC + i)) * HD + h * D);
    const float4* avs = (const float4*)(attn + ((size_t)(r * 2 + 0) * H + h) * D);
    float ss = 0.f;
#pragma unroll
    for (int j = 0; j < 8; j++) {
        float4 a = wsp[j], b = avs[j];
        ss += a.x * b.x + a.y * b.y + a.z * b.z + a.w * b.w;
    }
    g_as_cs[(size_t)r * NC * H + idx] = ss;
}

__global__ void adot_cs_dst_kernel(const float* __restrict__ attn) {
    int r = blockIdx.y;
    int idx = blockIdx.x * blockDim.x + threadIdx.x;
    if (idx >= NS * H) return;
    int i = idx >> 3, h = idx & 7;
    const float4* wdp = (const float4*)(g_Wh_in + (size_t)i * HD + h * D);
    const float4* avd = (const float4*)(attn + ((size_t)(r * 2 + 1) * H + h) * D);
    float sd = 0.f;
#pragma unroll
    for (int j = 0; j < 8; j++) {
        float4 a = wdp[j], b = avd[j];
        sd += a.x * b.x + a.y * b.y + a.z * b.z + a.w * b.w;
    }
    g_ad_cs[(size_t)r * NS * H + idx] = sd;
}

// ---------------- CSR build ----------------
__global__ void count_cc(const int* __restrict__ edst) {
    int r = blockIdx.y;
    int e = blockIdx.x * blockDim.x + threadIdx.x;
    if (e < ECC) atomicAdd(&g_cur_cc[r * NC + edst[(size_t)r * ECC + e]], 1);
}
__global__ void count_cs(const int* __restrict__ edst) {
    int r = blockIdx.y;
    int e = blockIdx.x * blockDim.x + threadIdx.x;
    if (e < ECS) atomicAdd(&g_cur_cs[r * NS + edst[(size_t)r * ECS + e]], 1);
}

// exclusive scan per relation; leaves cursors = offsets for scatter
__global__ void scan_kernel(int mode) {   // 0: cc (N=NC), 1: cs (N=NS)
    __shared__ int sd[1024];
    int t = threadIdx.x;
    int r = blockIdx.x;
    int N = (mode == 0) ? NC : NS;
    int* deg = (mode == 0) ? (g_cur_cc + r * NC) : (g_cur_cs + r * NS);
    int* off = (mode == 0) ? (g_off_cc + r * (NC + 1)) : (g_off_cs + r * (NS + 1));
    int carry = 0;
    for (int base = 0; base < N; base += 1024) {
        int idx = base + t;
        int v = (idx < N) ? deg[idx] : 0;
        sd[t] = v;
        __syncthreads();
        for (int o = 1; o < 1024; o <<= 1) {
            int x = (t >= o) ? sd[t - o] : 0;
            __syncthreads();
            sd[t] += x;
            __syncthreads();
        }
        int incl = sd[t];
        if (idx < N) { int ex = carry + incl - v; off[idx] = ex; deg[idx] = ex; }
        carry += sd[1023];
        __syncthreads();
    }
    if (t == 0) off[N] = carry;
}

__global__ void scatter_cc(const int* __restrict__ esrc, const int* __restrict__ edst) {
    int r = blockIdx.y;
    int e = blockIdx.x * blockDim.x + threadIdx.x;
    if (e >= ECC) return;
    int dst = edst[(size_t)r * ECC + e];
    int pos = atomicAdd(&g_cur_cc[r * NC + dst], 1);
    g_csr_cc[(size_t)r * ECC + pos] = esrc[(size_t)r * ECC + e];
}
__global__ void scatter_cs(const int* __restrict__ esrc, const int* __restrict__ edst) {
    int r = blockIdx.y;
    int e = blockIdx.x * blockDim.x + threadIdx.x;
    if (e >= ECS) return;
    int dst = edst[(size_t)r * ECS + e];
    int pos = atomicAdd(&g_cur_cs[r * NS + dst], 1);
    g_csr_cs[(size_t)r * ECS + pos] = esrc[(size_t)r * ECS + e];
}

// ---------------- per-destination aggregation (no atomics) ----------------
// warp per (dst_type d, node i): softmax denominator in registers, fused relu.
__global__ void agg_c(float* __restrict__ out) {
    int w = blockIdx.x * (blockDim.x >> 5) + (threadIdx.x >> 5);
    if (w >= 3 * NC) return;
    int lane = threadIdx.x & 31;
    int d = w / NC, i = w - d * NC;
    int h = lane >> 2;
    float acc[8];
#pragma unroll
    for (int k = 0; k < 8; k++) acc[k] = 0.f;
    for (int s = 0; s < 3; s++) {
        int r = 3 * s + d;
        int e0 = g_off_cc[r * (NC + 1) + i];
        int e1 = g_off_cc[r * (NC + 1) + i + 1];
        if (e0 == e1) continue;
        float ad = g_ad_cc[((size_t)r * NC + i) * H + h];
        const int* csr = g_csr_cc + (size_t)r * ECC;
        float ssum = 0.f;
        float pa[8];
#pragma unroll
        for (int k = 0; k < 8; k++) pa[k] = 0.f;
        for (int j = e0; j < e1; j++) {
            int src = csr[j];
            float as = g_as_cc[((size_t)r * NC + src) * H + h];
            float v = as + ad;
            v = v > 0.f ? v : ALPHA * v;
            float ex = __expf(v);
            ssum += ex;
            const float4* wh = (const float4*)(g_Wh_cc + ((size_t)r * NC + src) * HD + lane * 8);
            float4 w0 = wh[0], w1 = wh[1];
            pa[0] += ex * w0.x; pa[1] += ex * w0.y; pa[2] += ex * w0.z; pa[3] += ex * w0.w;
            pa[4] += ex * w1.x; pa[5] += ex * w1.y; pa[6] += ex * w1.z; pa[7] += ex * w1.w;
        }
        float inv = 1.f / ssum;
#pragma unroll
        for (int k = 0; k < 8; k++) acc[k] += pa[k] * inv;
    }
    float* ob = out + (size_t)d * OUT_C_N + (size_t)i * HD + lane * 8;
    float4 o0, o1;
    o0.x = fmaxf(acc[0], 0.f); o0.y = fmaxf(acc[1], 0.f);
    o0.z = fmaxf(acc[2], 0.f); o0.w = fmaxf(acc[3], 0.f);
    o1.x = fmaxf(acc[4], 0.f); o1.y = fmaxf(acc[5], 0.f);
    o1.z = fmaxf(acc[6], 0.f); o1.w = fmaxf(acc[7], 0.f);
    *(float4*)ob = o0;
    *(float4*)(ob + 4) = o1;
}

__global__ void agg_s(float* __restrict__ out) {
    int w = blockIdx.x * (blockDim.x >> 5) + (threadIdx.x >> 5);
    if (w >= NS) return;
    int lane = threadIdx.x & 31;
    int i = w;
    int h = lane >> 2;
    const float4* base = (const float4*)(g_Wh_in + (size_t)i * HD + lane * 8);
    float4 b0 = base[0], b1 = base[1];
    float acc[8] = {b0.x, b0.y, b0.z, b0.w, b1.x, b1.y, b1.z, b1.w};
    for (int r = 0; r < 3; r++) {
        int e0 = g_off_cs[r * (NS + 1) + i];
        int e1 = g_off_cs[r * (NS + 1) + i + 1];
        if (e0 == e1) continue;
        float ad = g_ad_cs[((size_t)r * NS + i) * H + h];
        const int* csr = g_csr_cs + (size_t)r * ECS;
        float ssum = 0.f;
        float pa[8];
#pragma unroll
        for (int k = 0; k < 8; k++) pa[k] = 0.f;
        for (int j = e0; j < e1; j++) {
            int src = csr[j];
            float as = g_as_cs[((size_t)r * NC + src) * H + h];
            float v = as + ad;
            v = v > 0.f ? v : ALPHA * v;
            float ex = __expf(v);
            ssum += ex;
            const float4* wh = (const float4*)(g_Wh_cs + ((size_t)r * NC + src) * HD + lane * 8);
            float4 w0 = wh[0], w1 = wh[1];
            pa[0] += ex * w0.x; pa[1] += ex * w0.y; pa[2] += ex * w0.z; pa[3] += ex * w0.w;
            pa[4] += ex * w1.x; pa[5] += ex * w1.y; pa[6] += ex * w1.z; pa[7] += ex * w1.w;
        }
        float inv = 1.f / ssum;
#pragma unroll
        for (int k = 0; k < 8; k++) acc[k] += pa[k] * inv;
    }
    float* ob = out + (size_t)OUT_S_OFF + (size_t)i * HD + lane * 8;
    float4 o0, o1;
    o0.x = fmaxf(acc[0], 0.f); o0.y = fmaxf(acc[1], 0.f);
    o0.z = fmaxf(acc[2], 0.f); o0.w = fmaxf(acc[3], 0.f);
    o1.x = fmaxf(acc[4], 0.f); o1.y = fmaxf(acc[5], 0.f);
    o1.z = fmaxf(acc[6], 0.f); o1.w = fmaxf(acc[7], 0.f);
    *(float4*)ob = o0;
    *(float4*)(ob + 4) = o1;
}

// ---------------- launch ----------------
extern "C" void kernel_launch(void* const* d_in, const int* in_sizes, int n_in,
                              void* d_out, int out_size) {
    const float* feat_C1 = (const float*)d_in[0];
    const float* feat_C2 = (const float*)d_in[1];
    const float* feat_C3 = (const float*)d_in[2];
    const float* feat_state = (const float*)d_in[3];
    const float* W_node = (const float*)d_in[4];
    const float* b_node = (const float*)d_in[5];
    const float* W_cc = (const float*)d_in[6];
    const float* b_cc = (const float*)d_in[7];
    const float* W_cs = (const float*)d_in[8];
    const float* b_cs = (const float*)d_in[9];
    const float* W_in = (const float*)d_in[10];
    const float* b_in = (const float*)d_in[11];
    const float* attn_cc = (const float*)d_in[12];
    const float* attn_cs = (const float*)d_in[13];
    const int* e_cc_src = (const int*)d_in[14];
    const int* e_cc_dst = (const int*)d_in[15];
    const int* e_cs_src = (const int*)d_in[16];
    const int* e_cs_dst = (const int*)d_in[17];
    float* out = (float*)d_out;
    (void)in_sizes; (void)n_in; (void)out_size;

    // CSR build (independent of GEMMs; cheap)
    zero_deg_kernel<<<128, 256>>>();
    dim3 gc1((ECC + 255) / 256, 9);
    count_cc<<<gc1, 256>>>(e_cc_dst);
    dim3 gc2((ECS + 255) / 256, 3);
    count_cs<<<gc2, 256>>>(e_cs_dst);
    scan_kernel<<<9, 1024>>>(0);
    scan_kernel<<<3, 1024>>>(1);
    scatter_cc<<<gc1, 256>>>(e_cc_src, e_cc_dst);
    scatter_cs<<<gc2, 256>>>(e_cs_src, e_cs_dst);

    // projections
    dim3 gg_cc((NC + 127) / 128, 2, 9);
    gemm128<<<gg_cc, 256>>>(feat_C1, feat_C2, feat_C3, feat_state, W_cc, b_cc, NC, 128, 0);
    dim3 gg_3((NC + 127) / 128, 2, 3);
    gemm128<<<gg_3, 256>>>(feat_C1, feat_C2, feat_C3, feat_state, W_node, b_node, NC, 128, 1);
    gemm128<<<gg_3, 256>>>(feat_C1, feat_C2, feat_C3, feat_state, W_cs, b_cs, NC, 128, 2);
    dim3 gg_in(NS / 128, 2, 1);
    gemm128<<<gg_in, 256>>>(feat_C1, feat_C2, feat_C3, feat_state, W_in, b_in, NS, 64, 3);

    // attention dots
    dim3 gadc((NC * H + 255) / 256, 9);
    adot_cc_kernel<<<gadc, 256>>>(attn_cc);
    dim3 gads((NC * H + 255) / 256, 3);
    adot_cs_src_kernel<<<gads, 256>>>(attn_cs);
    dim3 gadd((NS * H + 255) / 256, 3);
    adot_cs_dst_kernel<<<gadd, 256>>>(attn_cs);

    // per-destination aggregation, fused softmax + relu, no atomics
    agg_c<<<(3 * NC + 7) / 8, 256>>>(out);
    agg_s<<<(NS + 7) / 8, 256>>>(out);
}

// round 8
// speedup vs baseline: 1.5241x; 1.0079x over previous
#include <cuda_runtime.h>
#include <cstdint>

#define H 8
#define D 32
#define HD 256
#define NC 10000
#define NS 1024
#define ECC 120000
#define ECS 10000
#define ALPHA 0.2f

#define OUT_C_N   (NC * HD)
#define OUT_S_OFF (3 * OUT_C_N)

// ---------------- device scratch (static, allocation-free) ----------------
__device__ float g_Wh_cc[9 * NC * HD];
__device__ float g_Wh_cs[3 * NC * HD];
__device__ float g_Wh_node[3 * NC * HD];
__device__ float g_Wh_in[NS * HD];
__device__ float g_as_cc[9 * NC * H];
__device__ float g_ad_cc[9 * NC * H];
__device__ float g_as_cs[3 * NC * H];
__device__ float g_ad_cs[3 * NS * H];
// CSR scratch
__device__ int g_cur_cc[9 * NC];
__device__ int g_off_cc[9 * (NC + 1)];
__device__ int g_csr_cc[9 * ECC];
__device__ int g_cur_cs[3 * NS];
__device__ int g_off_cs[3 * (NS + 1)];
__device__ int g_csr_cs[3 * ECS];

// ---------------- helpers ----------------
__device__ __forceinline__ unsigned f2tf(float x) {
    unsigned r;
    asm("cvt.rna.tf32.f32 %0, %1;" : "=r"(r) : "f"(x));
    return r;
}

__device__ __forceinline__ void mma_tf32(float& c0, float& c1, float& c2, float& c3,
                                         unsigned a0, unsigned a1, unsigned a2, unsigned a3,
                                         unsigned b0, unsigned b1) {
    asm volatile("mma.sync.aligned.m16n8k8.row.col.f32.tf32.tf32.f32 "
                 "{%0,%1,%2,%3}, {%4,%5,%6,%7}, {%8,%9}, {%0,%1,%2,%3};"
                 : "+f"(c0), "+f"(c1), "+f"(c2), "+f"(c3)
                 : "r"(a0), "r"(a1), "r"(a2), "r"(a3), "r"(b0), "r"(b1));
}

// ---------------- zero degree counters ----------------
__global__ void zero_deg_kernel() {
    int i = blockIdx.x * blockDim.x + threadIdx.x;
    int stride = gridDim.x * blockDim.x;
    for (int j = i; j < 9 * NC; j += stride) g_cur_cc[j] = 0;
    for (int j = i; j < 3 * NS; j += stride) g_cur_cs[j] = 0;
}

// ---------------- tf32 tensor-core GEMM: C[M,256] = A[M,K] @ W[r][K,256] + b[r] ----
// CTA: 256 thr = 8 warps (4 m-groups x 2 n-groups), tile 128 rows x 128 cols.
// warp tile 32x64 = 2 m16-tiles x 8 n8-tiles, mma.m16n8k8.
// smem stores fragments in (tile, lane, reg) order: A-frag = 1 LDS.128, B-frag = 1 LDS.64.
// mode 0: cc->g_Wh_cc[r] (src r/3); 1: node->g_Wh_node[r]; 2: cs->g_Wh_cs[r]; 3: in->g_Wh_in.
// (outputs chosen via __device__ symbols in device code — never pass symbols from host)
__global__ __launch_bounds__(256, 2)
void gemm_tf32(const float* __restrict__ f0, const float* __restrict__ f1,
               const float* __restrict__ f2, const float* __restrict__ fs,
               const float* __restrict__ W, const float* __restrict__ Bb,
               int M, int K, int mode) {
    int r = blockIdx.z;
    const float* A;
    float* Cbase;
    if (mode == 3) { A = fs; Cbase = g_Wh_in; }
    else {
        int s = (mode == 0) ? (r / 3) : r;
        A = (s == 0) ? f0 : (s == 1) ? f1 : f2;
        float* base = (mode == 0) ? g_Wh_cc : (mode == 1) ? g_Wh_node : g_Wh_cs;
        Cbase = base + (size_t)r * NC * HD;
    }
    const float* Wr = W + (size_t)r * K * HD;
    const float* Br = Bb + (size_t)r * HD;

    __shared__ unsigned sA[2][1024];   // [stage][mt*128 + lane*4 + reg], 8 m16-tiles
    __shared__ unsigned sB[2][1024];   // [stage][nt*64 + lane*2 + reg], 16 n8-tiles

    int row0 = blockIdx.x * 128;
    int col0 = blockIdx.y * 128;
    int t = threadIdx.x;
    int lane = t & 31, wid = t >> 5;
    int wm = wid >> 1, wn = wid & 1;

    // staging indices
    int a_row = t >> 1, a_kh = t & 1;           // A: 128 rows x (2 x float4)
    int b_kr = t >> 5, b_col = (t & 31) * 4;    // B: 8 k-rows x 128 cols

    int nk = K >> 3;

    // ---- stage 0 load ----
    {
        int gr = row0 + a_row;
        float4 av = (gr < M) ? *(const float4*)(A + (size_t)gr * K + a_kh * 4)
                             : make_float4(0.f, 0.f, 0.f, 0.f);
        float va[4] = {av.x, av.y, av.z, av.w};
        int mt = a_row >> 4;
        int regbase = (a_kh << 1) | ((a_row >> 3) & 1);
#pragma unroll
        for (int j = 0; j < 4; j++) {
            int ln = ((a_row & 7) << 2) | j;
            sA[0][mt * 128 + ln * 4 + regbase] = f2tf(va[j]);
        }
        float4 bv = *(const float4*)(Wr + (size_t)b_kr * HD + col0 + b_col);
        float vb[4] = {bv.x, bv.y, bv.z, bv.w};
#pragma unroll
        for (int j = 0; j < 4; j++) {
            int c = b_col + j;
            int nt = c >> 3, nn = c & 7;
            sB[0][nt * 64 + ((nn << 2) | (b_kr & 3)) * 2 + (b_kr >> 2)] = f2tf(vb[j]);
        }
    }
    __syncthreads();

    float acc[2][8][4];
#pragma unroll
    for (int i = 0; i < 2; i++)
#pragma unroll
        for (int j = 0; j < 8; j++)
#pragma unroll
            for (int k = 0; k < 4; k++) acc[i][j][k] = 0.f;

    for (int kt = 0; kt < nk; kt++) {
        int cur = kt & 1;
        float4 an, bn;
        if (kt + 1 < nk) {
            int gr = row0 + a_row;
            an = (gr < M) ? *(const float4*)(A + (size_t)gr * K + (kt + 1) * 8 + a_kh * 4)
                          : make_float4(0.f, 0.f, 0.f, 0.f);
            bn = *(const float4*)(Wr + (size_t)((kt + 1) * 8 + b_kr) * HD + col0 + b_col);
        }
        // fragments
        uint4 af[2];
        uint2 bf[8];
#pragma unroll
        for (int i = 0; i < 2; i++)
            af[i] = *(const uint4*)&sA[cur][(wm * 2 + i) * 128 + lane * 4];
#pragma unroll
        for (int j = 0; j < 8; j++)
            bf[j] = *(const uint2*)&sB[cur][(wn * 8 + j) * 64 + lane * 2];
#pragma unroll
        for (int i = 0; i < 2; i++)
#pragma unroll
            for (int j = 0; j < 8; j++)
                mma_tf32(acc[i][j][0], acc[i][j][1], acc[i][j][2], acc[i][j][3],
                         af[i].x, af[i].y, af[i].z, af[i].w, bf[j].x, bf[j].y);

        if (kt + 1 < nk) {
            int nxt = cur ^ 1;
            float va[4] = {an.x, an.y, an.z, an.w};
            int mt = a_row >> 4;
            int regbase = (a_kh << 1) | ((a_row >> 3) & 1);
#pragma unroll
            for (int j = 0; j < 4; j++) {
                int ln = ((a_row & 7) << 2) | j;
                sA[nxt][mt * 128 + ln * 4 + regbase] = f2tf(va[j]);
            }
            float vb[4] = {bn.x, bn.y, bn.z, bn.w};
#pragma unroll
            for (int j = 0; j < 4; j++) {
                int c = b_col + j;
                int nt = c >> 3, nn = c & 7;
                sB[nxt][nt * 64 + ((nn << 2) | (b_kr & 3)) * 2 + (b_kr >> 2)] = f2tf(vb[j]);
            }
            __syncthreads();
        }
    }

    // ---- epilogue: bias + store ----
#pragma unroll
    for (int i = 0; i < 2; i++) {
        int gr0 = row0 + wm * 32 + i * 16 + (lane >> 2);
#pragma unroll
        for (int j = 0; j < 8; j++) {
            int gc = col0 + wn * 64 + j * 8 + (lane & 3) * 2;
            float2 bb = *(const float2*)(Br + gc);
            if (gr0 < M) {
                float2 o;
                o.x = acc[i][j][0] + bb.x;
                o.y = acc[i][j][1] + bb.y;
                *(float2*)(Cbase + (size_t)gr0 * HD + gc) = o;
            }
            if (gr0 + 8 < M) {
                float2 o;
                o.x = acc[i][j][2] + bb.x;
                o.y = acc[i][j][3] + bb.y;
                *(float2*)(Cbase + (size_t)(gr0 + 8) * HD + gc) = o;
            }
        }
    }
}

// ---------------- attention dot products ----------------
__global__ void adot_cc_kernel(const float* __restrict__ attn) {
    int r = blockIdx.y;
    int idx = blockIdx.x * blockDim.x + threadIdx.x;
    if (idx >= NC * H) return;
    int i = idx >> 3, h = idx & 7;
    const float4* wsp = (const float4*)(g_Wh_cc + ((size_t)(r * NC + i)) * HD + h * D);
    const float4* avs = (const float4*)(attn + ((size_t)(r * 2 + 0) * H + h) * D);
    const float4* wdp = (const float4*)(g_Wh_node + ((size_t)((r % 3) * NC + i)) * HD + h * D);
    const float4* avd = (const float4*)(attn + ((size_t)(r * 2 + 1) * H + h) * D);
    float ss = 0.f, sd = 0.f;
#pragma unroll
    for (int j = 0; j < 8; j++) {
        float4 a = wsp[j], b = avs[j];
        ss += a.x * b.x + a.y * b.y + a.z * b.z + a.w * b.w;
        float4 c = wdp[j], dv = avd[j];
        sd += c.x * dv.x + c.y * dv.y + c.z * dv.z + c.w * dv.w;
    }
    g_as_cc[(size_t)r * NC * H + idx] = ss;
    g_ad_cc[(size_t)r * NC * H + idx] = sd;
}

__global__ void adot_cs_src_kernel(const float* __restrict__ attn) {
    int r = blockIdx.y;
    int idx = blockIdx.x * blockDim.x + threadIdx.x;
    if (idx >= NC * H) return;
    int i = idx >> 3, h = idx & 7;
    const float4* wsp = (const float4*)(g_Wh_cs + ((size_t)(r * NC + i)) * HD + h * D);
    const float4* avs = (const float4*)(attn + ((size_t)(r * 2 + 0) * H + h) * D);
    float ss = 0.f;
#pragma unroll
    for (int j = 0; j < 8; j++) {
        float4 a = wsp[j], b = avs[j];
        ss += a.x * b.x + a.y * b.y + a.z * b.z + a.w * b.w;
    }
    g_as_cs[(size_t)r * NC * H + idx] = ss;
}

__global__ void adot_cs_dst_kernel(const float* __restrict__ attn) {
    int r = blockIdx.y;
    int idx = blockIdx.x * blockDim.x + threadIdx.x;
    if (idx >= NS * H) return;
    int i = idx >> 3, h = idx & 7;
    const float4* wdp = (const float4*)(g_Wh_in + (size_t)i * HD + h * D);
    const float4* avd = (const float4*)(attn + ((size_t)(r * 2 + 1) * H + h) * D);
    float sd = 0.f;
#pragma unroll
    for (int j = 0; j < 8; j++) {
        float4 a = wdp[j], b = avd[j];
        sd += a.x * b.x + a.y * b.y + a.z * b.z + a.w * b.w;
    }
    g_ad_cs[(size_t)r * NS * H + idx] = sd;
}

// ---------------- CSR build ----------------
__global__ void count_cc(const int* __restrict__ edst) {
    int r = blockIdx.y;
    int e = blockIdx.x * blockDim.x + threadIdx.x;
    if (e < ECC) atomicAdd(&g_cur_cc[r * NC + edst[(size_t)r * ECC + e]], 1);
}
__global__ void count_cs(const int* __restrict__ edst) {
    int r = blockIdx.y;
    int e = blockIdx.x * blockDim.x + threadIdx.x;
    if (e < ECS) atomicAdd(&g_cur_cs[r * NS + edst[(size_t)r * ECS + e]], 1);
}

// one launch, 12 blocks: blocks 0-8 scan cc relations, 9-11 scan cs relations.
// warp-shuffle scan, 3 syncthreads per 1024-chunk.
__global__ void scan_all() {
    int rb = blockIdx.x;
    int N;
    int* deg;
    int* off;
    if (rb < 9) { N = NC; deg = g_cur_cc + rb * NC; off = g_off_cc + rb * (NC + 1); }
    else { int r = rb - 9; N = NS; deg = g_cur_cs + r * NS; off = g_off_cs + r * (NS + 1); }
    __shared__ int wpart[32];
    __shared__ int stotal;
    int t = threadIdx.x, lane = t & 31, wid = t >> 5;
    int carry = 0;
    for (int base = 0; base < N; base += 1024) {
        int idx = base + t;
        int v = (idx < N) ? deg[idx] : 0;
        int s = v;
#pragma unroll
        for (int o = 1; o < 32; o <<= 1) {
            int x = __shfl_up_sync(0xFFFFFFFFu, s, o);
            if (lane >= o) s += x;
        }
        if (lane == 31) wpart[wid] = s;
        __syncthreads();
        if (wid == 0) {
            int p = wpart[lane];
            int q = p;
#pragma unroll
            for (int o = 1; o < 32; o <<= 1) {
                int x = __shfl_up_sync(0xFFFFFFFFu, q, o);
                if (lane >= o) q += x;
            }
            wpart[lane] = q - p;          // exclusive warp prefix
            if (lane == 31) stotal = q;   // block total
        }
        __syncthreads();
        int excl = carry + wpart[wid] + s - v;
        if (idx < N) { off[idx] = excl; deg[idx] = excl; }
        carry += stotal;
        __syncthreads();
    }
    if (t == 0) off[N] = carry;
}

__global__ void scatter_cc(const int* __restrict__ esrc, const int* __restrict__ edst) {
    int r = blockIdx.y;
    int e = blockIdx.x * blockDim.x + threadIdx.x;
    if (e >= ECC) return;
    int dst = edst[(size_t)r * ECC + e];
    int pos = atomicAdd(&g_cur_cc[r * NC + dst], 1);
    g_csr_cc[(size_t)r * ECC + pos] = esrc[(size_t)r * ECC + e];
}
__global__ void scatter_cs(const int* __restrict__ esrc, const int* __restrict__ edst) {
    int r = blockIdx.y;
    int e = blockIdx.x * blockDim.x + threadIdx.x;
    if (e >= ECS) return;
    int dst = edst[(size_t)r * ECS + e];
    int pos = atomicAdd(&g_cur_cs[r * NS + dst], 1);
    g_csr_cs[(size_t)r * ECS + pos] = esrc[(size_t)r * ECS + e];
}

// ---------------- per-destination aggregation (no atomics) ----------------
__global__ void agg_c(float* __restrict__ out) {
    int w = blockIdx.x * (blockDim.x >> 5) + (threadIdx.x >> 5);
    if (w >= 3 * NC) return;
    int lane = threadIdx.x & 31;
    int d = w / NC, i = w - d * NC;
    int h = lane >> 2;
    float acc[8];
#pragma unroll
    for (int k = 0; k < 8; k++) acc[k] = 0.f;
    for (int s = 0; s < 3; s++) {
        int r = 3 * s + d;
        int e0 = g_off_cc[r * (NC + 1) + i];
        int e1 = g_off_cc[r * (NC + 1) + i + 1];
        if (e0 == e1) continue;
        float ad = g_ad_cc[((size_t)r * NC + i) * H + h];
        const int* csr = g_csr_cc + (size_t)r * ECC;
        float ssum = 0.f;
        float pa[8];
#pragma unroll
        for (int k = 0; k < 8; k++) pa[k] = 0.f;
        for (int j = e0; j < e1; j++) {
            int src = csr[j];
            float as = g_as_cc[((size_t)r * NC + src) * H + h];
            float v = as + ad;
            v = v > 0.f ? v : ALPHA * v;
            float ex = __expf(v);
            ssum += ex;
            const float4* wh = (const float4*)(g_Wh_cc + ((size_t)r * NC + src) * HD + lane * 8);
            float4 w0 = wh[0], w1 = wh[1];
            pa[0] += ex * w0.x; pa[1] += ex * w0.y; pa[2] += ex * w0.z; pa[3] += ex * w0.w;
            pa[4] += ex * w1.x; pa[5] += ex * w1.y; pa[6] += ex * w1.z; pa[7] += ex * w1.w;
        }
        float inv = 1.f / ssum;
#pragma unroll
        for (int k = 0; k < 8; k++) acc[k] += pa[k] * inv;
    }
    float* ob = out + (size_t)d * OUT_C_N + (size_t)i * HD + lane * 8;
    float4 o0, o1;
    o0.x = fmaxf(acc[0], 0.f); o0.y = fmaxf(acc[1], 0.f);
    o0.z = fmaxf(acc[2], 0.f); o0.w = fmaxf(acc[3], 0.f);
    o1.x = fmaxf(acc[4], 0.f); o1.y = fmaxf(acc[5], 0.f);
    o1.z = fmaxf(acc[6], 0.f); o1.w = fmaxf(acc[7], 0.f);
    *(float4*)ob = o0;
    *(float4*)(ob + 4) = o1;
}

__global__ void agg_s(float* __restrict__ out) {
    int w = blockIdx.x * (blockDim.x >> 5) + (threadIdx.x >> 5);
    if (w >= NS) return;
    int lane = threadIdx.x & 31;
    int i = w;
    int h = lane >> 2;
    const float4* base = (const float4*)(g_Wh_in + (size_t)i * HD + lane * 8);
    float4 b0 = base[0], b1 = base[1];
    float acc[8] = {b0.x, b0.y, b0.z, b0.w, b1.x, b1.y, b1.z, b1.w};
    for (int r = 0; r < 3; r++) {
        int e0 = g_off_cs[r * (NS + 1) + i];
        int e1 = g_off_cs[r * (NS + 1) + i + 1];
        if (e0 == e1) continue;
        float ad = g_ad_cs[((size_t)r * NS + i) * H + h];
        const int* csr = g_csr_cs + (size_t)r * ECS;
        float ssum = 0.f;
        float pa[8];
#pragma unroll
        for (int k = 0; k < 8; k++) pa[k] = 0.f;
        for (int j = e0; j < e1; j++) {
            int src = csr[j];
            float as = g_as_cs[((size_t)r * NC + src) * H + h];
            float v = as + ad;
            v = v > 0.f ? v : ALPHA * v;
            float ex = __expf(v);
            ssum += ex;
            const float4* wh = (const float4*)(g_Wh_cs + ((size_t)r * NC + src) * HD + lane * 8);
            float4 w0 = wh[0], w1 = wh[1];
            pa[0] += ex * w0.x; pa[1] += ex * w0.y; pa[2] += ex * w0.z; pa[3] += ex * w0.w;
            pa[4] += ex * w1.x; pa[5] += ex * w1.y; pa[6] += ex * w1.z; pa[7] += ex * w1.w;
        }
        float inv = 1.f / ssum;
#pragma unroll
        for (int k = 0; k < 8; k++) acc[k] += pa[k] * inv;
    }
    float* ob = out + (size_t)OUT_S_OFF + (size_t)i * HD + lane * 8;
    float4 o0, o1;
    o0.x = fmaxf(acc[0], 0.f); o0.y = fmaxf(acc[1], 0.f);
    o0.z = fmaxf(acc[2], 0.f); o0.w = fmaxf(acc[3], 0.f);
    o1.x = fmaxf(acc[4], 0.f); o1.y = fmaxf(acc[5], 0.f);
    o1.z = fmaxf(acc[6], 0.f); o1.w = fmaxf(acc[7], 0.f);
    *(float4*)ob = o0;
    *(float4*)(ob + 4) = o1;
}

// ---------------- launch ----------------
extern "C" void kernel_launch(void* const* d_in, const int* in_sizes, int n_in,
                              void* d_out, int out_size) {
    const float* feat_C1 = (const float*)d_in[0];
    const float* feat_C2 = (const float*)d_in[1];
    const float* feat_C3 = (const float*)d_in[2];
    const float* feat_state = (const float*)d_in[3];
    const float* W_node = (const float*)d_in[4];
    const float* b_node = (const float*)d_in[5];
    const float* W_cc = (const float*)d_in[6];
    const float* b_cc = (const float*)d_in[7];
    const float* W_cs = (const float*)d_in[8];
    const float* b_cs = (const float*)d_in[9];
    const float* W_in = (const float*)d_in[10];
    const float* b_in = (const float*)d_in[11];
    const float* attn_cc = (const float*)d_in[12];
    const float* attn_cs = (const float*)d_in[13];
    const int* e_cc_src = (const int*)d_in[14];
    const int* e_cc_dst = (const int*)d_in[15];
    const int* e_cs_src = (const int*)d_in[16];
    const int* e_cs_dst = (const int*)d_in[17];
    float* out = (float*)d_out;
    (void)in_sizes; (void)n_in; (void)out_size;

    // CSR build
    zero_deg_kernel<<<128, 256>>>();
    dim3 gc1((ECC + 255) / 256, 9);
    count_cc<<<gc1, 256>>>(e_cc_dst);
    dim3 gc2((ECS + 255) / 256, 3);
    count_cs<<<gc2, 256>>>(e_cs_dst);
    scan_all<<<12, 1024>>>();
    scatter_cc<<<gc1, 256>>>(e_cc_src, e_cc_dst);
    scatter_cs<<<gc2, 256>>>(e_cs_src, e_cs_dst);

    // projections (tf32 tensor cores)
    dim3 gg_cc((NC + 127) / 128, 2, 9);
    gemm_tf32<<<gg_cc, 256>>>(feat_C1, feat_C2, feat_C3, feat_state, W_cc, b_cc, NC, 128, 0);
    dim3 gg_3((NC + 127) / 128, 2, 3);
    gemm_tf32<<<gg_3, 256>>>(feat_C1, feat_C2, feat_C3, feat_state, W_node, b_node, NC, 128, 1);
    gemm_tf32<<<gg_3, 256>>>(feat_C1, feat_C2, feat_C3, feat_state, W_cs, b_cs, NC, 128, 2);
    dim3 gg_in((NS + 127) / 128, 2, 1);
    gemm_tf32<<<gg_in, 256>>>(feat_C1, feat_C2, feat_C3, feat_state, W_in, b_in, NS, 64, 3);

    // attention dots
    dim3 gadc((NC * H + 255) / 256, 9);
    adot_cc_kernel<<<gadc, 256>>>(attn_cc);
    dim3 gads((NC * H + 255) / 256, 3);
    adot_cs_src_kernel<<<gads, 256>>>(attn_cs);
    dim3 gadd((NS * H + 255) / 256, 3);
    adot_cs_dst_kernel<<<gadd, 256>>>(attn_cs);

    // per-destination aggregation, fused softmax + relu, no atomics
    agg_c<<<(3 * NC + 7) / 8, 256>>>(out);
    agg_s<<<(NS + 7) / 8, 256>>>(out);
}